// round 11
// baseline (speedup 1.0000x reference)
#include <cuda_runtime.h>

#define IMG 224
#define NPIX (IMG * IMG)        // 50176
#define NUM_VIEWS 6
#define NBATCH 16
#define NPTS 32768
#define THREADS 1024
#define NGROUPS (NPTS / 4)          // 8192 float4-groups of 4 points
#define NITERS (NGROUPS / THREADS)  // 8 iterations, exact

// order-preserving float->uint (finite floats; -inf -> 0 so 0 is "empty")
__device__ __forceinline__ unsigned f2mono(float f) {
    unsigned b = __float_as_uint(f);
    return b ^ (((int)b >> 31) | 0x80000000u);
}
__device__ __forceinline__ float mono2f(unsigned u) {
    return __uint_as_float(u ^ (((int)(~u) >> 31) | 0x80000000u));
}

__global__ __launch_bounds__(THREADS, 1)
void render_kernel(const float* __restrict__ points, float* __restrict__ out) {
    extern __shared__ unsigned simg[];       // NPIX mono-encoded zf (0 = empty)
    __shared__ float red_min[32], red_max[32];

    const int bv  = blockIdx.x;
    const int b   = bv / NUM_VIEWS;
    const int v   = bv % NUM_VIEWS;
    const int tid = threadIdx.x;
    const int wid = tid >> 5, lid = tid & 31;

    const float deg2rad = 0.017453292519943295f;
    const float a = (float)(v * 60) * deg2rad;
    const float el_tab[NUM_VIEWS] = {0.f, 30.f, -30.f, 0.f, 0.f, 0.f};
    const float e = el_tab[v] * deg2rad;
    const float ca = cosf(a), sa = sinf(a), ce = cosf(e), se = sinf(e);

    const float4* __restrict__ pb4 =
        (const float4*)(points + (size_t)b * NPTS * 3);

    // zero the image
    {
        uint4 zv = make_uint4(0u, 0u, 0u, 0u);
        uint4* s4 = (uint4*)simg;
        for (int i = tid; i < NPIX / 4; i += THREADS) s4[i] = zv;
    }
    __syncthreads();

    // ---- SINGLE pass: rotate, splat mono(zf), accumulate zmin/zmax ----
    const float off0 = -2.0f / 224.0f;
    const float off4 =  2.0f / 224.0f;
    float zmn = INFINITY, zmx = -INFINITY;

    {
        float4 c0 = pb4[3 * tid + 0];
        float4 c1 = pb4[3 * tid + 1];
        float4 c2 = pb4[3 * tid + 2];
        #pragma unroll 1
        for (int it = 0; it < NITERS; it++) {
            float4 n0, n1, n2;
            if (it < NITERS - 1) {
                int gn = 3 * (tid + (it + 1) * THREADS);
                n0 = pb4[gn + 0];
                n1 = pb4[gn + 1];
                n2 = pb4[gn + 2];
            }
            float xs[4] = {c0.x, c0.w, c1.z, c2.y};
            float ys[4] = {c0.y, c1.x, c1.w, c2.z};
            float zs[4] = {c0.z, c1.y, c2.x, c2.w};
            #pragma unroll
            for (int k = 0; k < 4; k++) {
                float x = xs[k], y = ys[k], z = zs[k];
                float xr = x * ca - z * sa;
                float zr = x * sa + z * ca;
                float yr = y * ce - zr * se;
                float zf = y * se + zr * ce;

                zmn = fminf(zmn, zf);
                zmx = fmaxf(zmx, zf);

                // identical fp expressions to the reference path (bit-exact
                // pixel coverage)
                int px0 = (int)((xr + off0 + 1.0f) * 0.5f * (float)(IMG - 1));
                int px4 = (int)((xr + off4 + 1.0f) * 0.5f * (float)(IMG - 1));
                int py0 = (int)((yr + off0 + 1.0f) * 0.5f * (float)(IMG - 1));
                int py4 = (int)((yr + off4 + 1.0f) * 0.5f * (float)(IMG - 1));

                int xlo = max(px0, 0), xhi = min(px4, IMG - 1);
                int ylo = max(py0, 0), yhi = min(py4, IMG - 1);
                if (xlo > xhi || ylo > yhi) continue;

                // splat the ORDER of zf; rescale to feat happens in epilogue
                // (feat is monotone in zf, shared zmn/scale -> max commutes)
                unsigned fb = f2mono(zf);

                // rect extent <= 3 per axis; min-clamp collapses the unrolled
                // 3x3 onto the exact valid rect (duplicates idempotent under max)
                int x1 = min(xlo + 1, xhi);
                int y1 = min(ylo + 1, yhi);
                int rA = ylo * IMG, rB = y1 * IMG, rC = yhi * IMG;
                atomicMax(&simg[rA + xlo], fb);
                atomicMax(&simg[rA + x1 ], fb);
                atomicMax(&simg[rA + xhi], fb);
                atomicMax(&simg[rB + xlo], fb);
                atomicMax(&simg[rB + x1 ], fb);
                atomicMax(&simg[rB + xhi], fb);
                atomicMax(&simg[rC + xlo], fb);
                atomicMax(&simg[rC + x1 ], fb);
                atomicMax(&simg[rC + xhi], fb);
            }
            c0 = n0; c1 = n1; c2 = n2;
        }
    }

    // block reduction of zmn/zmx (overlaps with atomic drain)
    #pragma unroll
    for (int o = 16; o > 0; o >>= 1) {
        zmn = fminf(zmn, __shfl_xor_sync(0xffffffffu, zmn, o));
        zmx = fmaxf(zmx, __shfl_xor_sync(0xffffffffu, zmx, o));
    }
    if (lid == 0) { red_min[wid] = zmn; red_max[wid] = zmx; }
    __syncthreads();
    if (wid == 0) {
        zmn = red_min[lid];
        zmx = red_max[lid];
        #pragma unroll
        for (int o = 16; o > 0; o >>= 1) {
            zmn = fminf(zmn, __shfl_xor_sync(0xffffffffu, zmn, o));
            zmx = fmaxf(zmx, __shfl_xor_sync(0xffffffffu, zmx, o));
        }
        if (lid == 0) { red_min[0] = zmn; red_max[0] = zmx; }
    }
    __syncthreads();
    zmn = red_min[0];
    const float scale = 0.7f / (red_max[0] - zmn + 1e-6f);

    // ---- Epilogue: decode + rescale + broadcast to 3 channels ----
    float* __restrict__ ob = out + (size_t)bv * 3 * NPIX;
    float4* __restrict__ ob4 = (float4*)ob;
    const uint4* __restrict__ s4 = (const uint4*)simg;
    for (int i = tid; i < NPIX / 4; i += THREADS) {
        uint4 u = s4[i];
        float4 val;
        val.x = u.x ? (0.3f + (mono2f(u.x) - zmn) * scale) : 0.0f;
        val.y = u.y ? (0.3f + (mono2f(u.y) - zmn) * scale) : 0.0f;
        val.z = u.z ? (0.3f + (mono2f(u.z) - zmn) * scale) : 0.0f;
        val.w = u.w ? (0.3f + (mono2f(u.w) - zmn) * scale) : 0.0f;
        ob4[i]                = val;
        ob4[i + NPIX / 4]     = val;
        ob4[i + 2 * NPIX / 4] = val;
    }
}

extern "C" void kernel_launch(void* const* d_in, const int* in_sizes, int n_in,
                              void* d_out, int out_size) {
    const float* points = (const float*)d_in[0];
    float* out = (float*)d_out;

    const size_t smem = (size_t)NPIX * sizeof(unsigned);  // 200704 bytes
    cudaFuncSetAttribute(render_kernel,
                         cudaFuncAttributeMaxDynamicSharedMemorySize, (int)smem);

    render_kernel<<<NBATCH * NUM_VIEWS, THREADS, smem>>>(points, out);
}

// round 13
// speedup vs baseline: 1.4321x; 1.4321x over previous
#include <cuda_runtime.h>

#define IMG 224
#define NPIX (IMG * IMG)        // 50176
#define NUM_VIEWS 6
#define NBATCH 16
#define NPTS 32768
#define THREADS 1024
#define NGROUPS (NPTS / 4)          // 8192 float4-groups of 4 points
#define NITERS (NGROUPS / THREADS)  // 8 iterations, exact
#define NQ4 (NPIX / 4)              // 12544 float4 slots in the image

__global__ __launch_bounds__(THREADS, 1)
void render_kernel(const float* __restrict__ points, float* __restrict__ out) {
    extern __shared__ float simg[];          // NPIX floats (image accumulator)
    __shared__ float red_min[32], red_max[32];

    const int bv  = blockIdx.x;
    const int b   = bv / NUM_VIEWS;
    const int v   = bv % NUM_VIEWS;
    const int tid = threadIdx.x;
    const int wid = tid >> 5, lid = tid & 31;

    const float deg2rad = 0.017453292519943295f;
    const float a = (float)(v * 60) * deg2rad;
    const float el_tab[NUM_VIEWS] = {0.f, 30.f, -30.f, 0.f, 0.f, 0.f};
    const float e = el_tab[v] * deg2rad;
    const float ca = cosf(a), sa = sinf(a), ce = cosf(e), se = sinf(e);
    // fused z_fin coefficients (pass 1 only; perturbs zmin/zmax by ulps)
    const float kx = sa * ce, ky = se, kz = ca * ce;

    const float4* __restrict__ pb4 =
        (const float4*)(points + (size_t)b * NPTS * 3);

    // ---- Pass 1: zmin/zmax of z_fin, double-buffered loads; the shared-image
    // zeroing is folded into the loop so STS work hides the cold DRAM latency.
    float zmn = INFINITY, zmx = -INFINITY;
    {
        float4* s4 = (float4*)simg;
        const float4 zv = make_float4(0.f, 0.f, 0.f, 0.f);
        float4 c0 = pb4[3 * tid + 0];
        float4 c1 = pb4[3 * tid + 1];
        float4 c2 = pb4[3 * tid + 2];
        #pragma unroll 1
        for (int it = 0; it < NITERS; it++) {
            float4 n0, n1, n2;
            if (it < NITERS - 1) {
                int gn = 3 * (tid + (it + 1) * THREADS);
                n0 = pb4[gn + 0];
                n1 = pb4[gn + 1];
                n2 = pb4[gn + 2];
            }
            // zero two image slices (2048 float4 / iter covers 12544 in 8 iters)
            int zi = tid + it * 2048;
            if (zi < NQ4) s4[zi] = zv;
            zi += 1024;
            if (zi < NQ4) s4[zi] = zv;

            float xs[4] = {c0.x, c0.w, c1.z, c2.y};
            float ys[4] = {c0.y, c1.x, c1.w, c2.z};
            float zs[4] = {c0.z, c1.y, c2.x, c2.w};
            #pragma unroll
            for (int k = 0; k < 4; k++) {
                float zf = xs[k] * kx + ys[k] * ky + zs[k] * kz;
                zmn = fminf(zmn, zf);
                zmx = fmaxf(zmx, zf);
            }
            c0 = n0; c1 = n1; c2 = n2;
        }
    }
    #pragma unroll
    for (int o = 16; o > 0; o >>= 1) {
        zmn = fminf(zmn, __shfl_xor_sync(0xffffffffu, zmn, o));
        zmx = fmaxf(zmx, __shfl_xor_sync(0xffffffffu, zmx, o));
    }
    if (lid == 0) { red_min[wid] = zmn; red_max[wid] = zmx; }
    __syncthreads();
    if (wid == 0) {
        zmn = red_min[lid];
        zmx = red_max[lid];
        #pragma unroll
        for (int o = 16; o > 0; o >>= 1) {
            zmn = fminf(zmn, __shfl_xor_sync(0xffffffffu, zmn, o));
            zmx = fmaxf(zmx, __shfl_xor_sync(0xffffffffu, zmx, o));
        }
        if (lid == 0) { red_min[0] = zmn; red_max[0] = zmx; }
    }
    __syncthreads();
    zmn = red_min[0];
    const float scale = 0.7f / (red_max[0] - zmn + 1e-6f);   // hoisted reciprocal
    const float fc = 0.3f - zmn * scale;                     // feat = zf*scale + fc

    // ---- Pass 2: rotate + branch-free 3x3 splat, double-buffered loads ----
    const float off0 = -2.0f / 224.0f;
    const float off4 =  2.0f / 224.0f;
    int* iimg = (int*)simg;

    {
        float4 c0 = pb4[3 * tid + 0];
        float4 c1 = pb4[3 * tid + 1];
        float4 c2 = pb4[3 * tid + 2];
        #pragma unroll 1
        for (int it = 0; it < NITERS; it++) {
            float4 n0, n1, n2;
            if (it < NITERS - 1) {
                int gn = 3 * (tid + (it + 1) * THREADS);
                n0 = pb4[gn + 0];
                n1 = pb4[gn + 1];
                n2 = pb4[gn + 2];
            }
            float xs[4] = {c0.x, c0.w, c1.z, c2.y};
            float ys[4] = {c0.y, c1.x, c1.w, c2.z};
            float zs[4] = {c0.z, c1.y, c2.x, c2.w};
            #pragma unroll
            for (int k = 0; k < 4; k++) {
                float x = xs[k], y = ys[k], z = zs[k];
                float xr = x * ca - z * sa;
                float zr = x * sa + z * ca;
                float yr = y * ce - zr * se;
                float zf = y * se + zr * ce;

                // identical fp expressions to the reference path (bit-exact
                // pixel coverage)
                int px0 = (int)((xr + off0 + 1.0f) * 0.5f * (float)(IMG - 1));
                int px4 = (int)((xr + off4 + 1.0f) * 0.5f * (float)(IMG - 1));
                int py0 = (int)((yr + off0 + 1.0f) * 0.5f * (float)(IMG - 1));
                int py4 = (int)((yr + off4 + 1.0f) * 0.5f * (float)(IMG - 1));

                int xlo = max(px0, 0), xhi = min(px4, IMG - 1);
                int ylo = max(py0, 0), yhi = min(py4, IMG - 1);
                if (xlo > xhi || ylo > yhi) continue;

                float feat = fmaf(zf, scale, fc);   // in [0.3, 1.0]
                int fb = __float_as_int(feat);      // positive floats order as ints

                // rect extent <= 3 per axis; min-clamp collapses the unrolled
                // 3x3 onto the exact valid rect (duplicates idempotent under max)
                int x1 = min(xlo + 1, xhi);
                int y1 = min(ylo + 1, yhi);
                int rA = ylo * IMG, rB = y1 * IMG, rC = yhi * IMG;
                atomicMax(&iimg[rA + xlo], fb);
                atomicMax(&iimg[rA + x1 ], fb);
                atomicMax(&iimg[rA + xhi], fb);
                atomicMax(&iimg[rB + xlo], fb);
                atomicMax(&iimg[rB + x1 ], fb);
                atomicMax(&iimg[rB + xhi], fb);
                atomicMax(&iimg[rC + xlo], fb);
                atomicMax(&iimg[rC + x1 ], fb);
                atomicMax(&iimg[rC + xhi], fb);
            }
            c0 = n0; c1 = n1; c2 = n2;
        }
    }
    __syncthreads();

    // ---- Epilogue: broadcast image to 3 channels of out[b][v][c][h][w] ----
    float* __restrict__ ob = out + (size_t)bv * 3 * NPIX;
    float4* __restrict__ ob4 = (float4*)ob;
    const float4* __restrict__ s4 = (const float4*)simg;
    for (int i = tid; i < NQ4; i += THREADS) {
        float4 val = s4[i];
        ob4[i]           = val;
        ob4[i + NQ4]     = val;
        ob4[i + 2 * NQ4] = val;
    }
}

extern "C" void kernel_launch(void* const* d_in, const int* in_sizes, int n_in,
                              void* d_out, int out_size) {
    const float* points = (const float*)d_in[0];
    float* out = (float*)d_out;

    const size_t smem = (size_t)NPIX * sizeof(float);  // 200704 bytes
    cudaFuncSetAttribute(render_kernel,
                         cudaFuncAttributeMaxDynamicSharedMemorySize, (int)smem);

    render_kernel<<<NBATCH * NUM_VIEWS, THREADS, smem>>>(points, out);
}